// round 4
// baseline (speedup 1.0000x reference)
#include <cuda_runtime.h>
#include <cstdint>

// Problem constants
#define Bq     8
#define NIN    512
#define NOUT   1024
#define Cc     16
#define OUTC   32
#define KW     5

// Conv tiling
#define CNTILE 64
#define CTHREADS 256

// Fused gauss+linear tiling
#define MTILE  64                 // m targets per block (2 per thread)
#define MT     (NOUT / MTILE)     // 16
#define GWARPS 16
#define NPW    (NIN / GWARPS)     // 32
#define GTHREADS (GWARPS * 32)    // 512
#define RSETS  8                  // partial sets in smem (staged reduce)

#define LOG2E 1.4426950408889634f

__device__ float g_rt[Bq * NIN * Cc];   // conv output [b][n][c]

__device__ __forceinline__ void ffma2(uint64_t& d, uint64_t a, uint64_t b) {
    asm("fma.rn.f32x2 %0, %1, %2, %0;" : "+l"(d) : "l"(a), "l"(b));
}
__device__ __forceinline__ uint64_t pack2(float lo, float hi) {
    uint64_t r; asm("mov.b64 %0, {%1, %2};" : "=l"(r) : "f"(lo), "f"(hi)); return r;
}
__device__ __forceinline__ void unpack2(uint64_t v, float& lo, float& hi) {
    asm("mov.b64 {%0, %1}, %2;" : "=f"(lo), "=f"(hi) : "l"(v));
}
__device__ __forceinline__ float ex2a(float x) {
    float r; asm("ex2.approx.f32 %0, %1;" : "=f"(r) : "f"(x)); return r;
}

// ---------------------------------------------------------------------------
// Kernel 1: Conv1d (NCH, OIH, SAME pad=2) + bias -> g_rt[b][n][c]
// ---------------------------------------------------------------------------
__global__ void conv_kernel(const float* __restrict__ r,
                            const float* __restrict__ w,
                            const float* __restrict__ bias) {
    __shared__ float sr[Cc][CNTILE + 4];
    __shared__ float sws[Cc * KW * Cc];   // [ci][k][c_out]
    __shared__ float sb[Cc];

    const int b  = blockIdx.y;
    const int n0 = blockIdx.x * CNTILE;
    const int t  = threadIdx.x;

    for (int i = t; i < Cc * (CNTILE + 4); i += CTHREADS) {
        int ci = i / (CNTILE + 4);
        int j  = i % (CNTILE + 4);
        int n  = n0 + j - 2;
        sr[ci][j] = (n >= 0 && n < NIN) ? r[((size_t)b * Cc + ci) * NIN + n] : 0.0f;
    }
    for (int i = t; i < Cc * Cc * KW; i += CTHREADS) {
        int c  = i / (Cc * KW);
        int rm = i % (Cc * KW);
        int ci = rm / KW;
        int k  = rm % KW;
        sws[(ci * KW + k) * Cc + c] = w[i];
    }
    if (t < Cc) sb[t] = bias[t];
    __syncthreads();

    const int nl = t & (CNTILE - 1);
    const int cg = t >> 6;

    float4 a;
    a.x = sb[cg * 4 + 0]; a.y = sb[cg * 4 + 1];
    a.z = sb[cg * 4 + 2]; a.w = sb[cg * 4 + 3];

    #pragma unroll
    for (int k = 0; k < KW; k++) {
        #pragma unroll
        for (int ci = 0; ci < Cc; ci++) {
            float v = sr[ci][nl + k];
            float4 wv = *reinterpret_cast<const float4*>(&sws[(ci * KW + k) * Cc + cg * 4]);
            a.x += v * wv.x; a.y += v * wv.y; a.z += v * wv.z; a.w += v * wv.w;
        }
    }

    *reinterpret_cast<float4*>(g_rt + ((size_t)b * NIN + n0 + nl) * Cc + cg * 4) = a;
}

// ---------------------------------------------------------------------------
// Kernel 2: fused Gaussian transform + staged reduce + pointwise linear.
// grid (MT, B) = (16, 8) = 128 blocks, block 512 (16 warps, 4/SMSP).
// Warp = n-chunk of 32, lane = m-pair {m0 = mt*64+lane, m1 = m0+32}.
// Staged reduction: warps 8-15 write partials, warps 0-7 fold theirs in,
// then 8-way tree. Keeps smem at ~68 KB.
// ---------------------------------------------------------------------------
__global__ void __launch_bounds__(GTHREADS, 1)
gauss_lin_kernel(const float* __restrict__ xc,
                 const float* __restrict__ xt,
                 const float* __restrict__ sigma,
                 const float* __restrict__ lw,
                 const float* __restrict__ lb,
                 float* __restrict__ out) {
    __shared__ float shx[NIN];                                 // 2 KB
    __shared__ __align__(16) float shrt[NIN][Cc];              // 32 KB
    __shared__ __align__(16) float red[RSETS * MTILE * Cc];    // 32 KB
    __shared__ float shlw[OUTC * Cc];                          // 2 KB
    __shared__ float sh_nh[Cc];
    __shared__ int   sh_alleq;

    const int b  = blockIdx.y;
    const int mt = blockIdx.x;
    const int t  = threadIdx.x;
    const int lane = t & 31;
    const int wid  = t >> 5;

    if (t < Cc) {
        float sg = sigma[t];
        sh_nh[t] = -0.5f * expf(-2.0f * sg) * LOG2E;  // fold log2e for ex2
    }
    if (t == 0) {
        float s0 = sigma[0];
        int eq = 1;
        #pragma unroll
        for (int c = 1; c < Cc; c++) eq &= (sigma[c] == s0);
        sh_alleq = eq;
    }
    for (int i = t; i < NIN; i += GTHREADS) shx[i] = xc[(size_t)b * NIN + i];
    {
        const float4* src = reinterpret_cast<const float4*>(g_rt + (size_t)b * NIN * Cc);
        float4* dst = reinterpret_cast<float4*>(&shrt[0][0]);
        #pragma unroll
        for (int i = t; i < NIN * Cc / 4; i += GTHREADS) dst[i] = src[i];
    }
    for (int i = t; i < OUTC * Cc; i += GTHREADS) shlw[i] = lw[i];
    __syncthreads();

    const int m0 = mt * MTILE + lane;
    const int m1 = m0 + 32;
    const float xm0 = xt[(size_t)b * NOUT + m0];
    const float xm1 = xt[(size_t)b * NOUT + m1];

    uint64_t a0[8], a1[8];
    #pragma unroll
    for (int p = 0; p < 8; p++) { a0[p] = 0ull; a1[p] = 0ull; }

    const int n0 = wid * NPW;

    if (sh_alleq) {
        const float nh = sh_nh[0];
        #pragma unroll 4
        for (int i = 0; i < NPW; i++) {
            const int n = n0 + i;
            const float xn = shx[n];                              // broadcast
            float d0 = xm0 - xn, d1 = xm1 - xn;
            float e0 = ex2a(d0 * d0 * nh);
            float e1 = ex2a(d1 * d1 * nh);
            uint64_t e0p = pack2(e0, e0);
            uint64_t e1p = pack2(e1, e1);
            const ulonglong2* rp = reinterpret_cast<const ulonglong2*>(shrt[n]);
            ulonglong2 q0 = rp[0], q1 = rp[1], q2 = rp[2], q3 = rp[3];
            ffma2(a0[0], e0p, q0.x); ffma2(a0[1], e0p, q0.y);
            ffma2(a0[2], e0p, q1.x); ffma2(a0[3], e0p, q1.y);
            ffma2(a0[4], e0p, q2.x); ffma2(a0[5], e0p, q2.y);
            ffma2(a0[6], e0p, q3.x); ffma2(a0[7], e0p, q3.y);
            ffma2(a1[0], e1p, q0.x); ffma2(a1[1], e1p, q0.y);
            ffma2(a1[2], e1p, q1.x); ffma2(a1[3], e1p, q1.y);
            ffma2(a1[4], e1p, q2.x); ffma2(a1[5], e1p, q2.y);
            ffma2(a1[6], e1p, q3.x); ffma2(a1[7], e1p, q3.y);
        }
    } else {
        float nh[Cc];
        #pragma unroll
        for (int c = 0; c < Cc; c++) nh[c] = sh_nh[c];
        for (int i = 0; i < NPW; i++) {
            const int n = n0 + i;
            const float xn = shx[n];
            float d0 = (xm0 - xn) * (xm0 - xn);
            float d1 = (xm1 - xn) * (xm1 - xn);
            const ulonglong2* rp = reinterpret_cast<const ulonglong2*>(shrt[n]);
            ulonglong2 q[4] = {rp[0], rp[1], rp[2], rp[3]};
            #pragma unroll
            for (int p = 0; p < 8; p++) {
                uint64_t qv = (p & 1) ? ((const ulonglong2*)q)[p >> 1].y
                                      : ((const ulonglong2*)q)[p >> 1].x;
                uint64_t e0p = pack2(ex2a(d0 * nh[2 * p]), ex2a(d0 * nh[2 * p + 1]));
                uint64_t e1p = pack2(ex2a(d1 * nh[2 * p]), ex2a(d1 * nh[2 * p + 1]));
                ffma2(a0[p], e0p, qv);
                ffma2(a1[p], e1p, qv);
            }
        }
    }

    // --- staged reduction into RSETS=8 partial sets -------------------------
    // Stage 1: warps 8..15 write their partials to red[wid-8].
    if (wid >= RSETS) {
        float v[Cc];
        #pragma unroll
        for (int p = 0; p < 8; p++) unpack2(a0[p], v[2 * p], v[2 * p + 1]);
        float* rp0 = red + ((size_t)(wid - RSETS) * MTILE + lane) * Cc;
        #pragma unroll
        for (int c = 0; c < Cc; c += 4)
            *reinterpret_cast<float4*>(rp0 + c) =
                make_float4(v[c], v[c + 1], v[c + 2], v[c + 3]);
        #pragma unroll
        for (int p = 0; p < 8; p++) unpack2(a1[p], v[2 * p], v[2 * p + 1]);
        float* rp1 = red + ((size_t)(wid - RSETS) * MTILE + lane + 32) * Cc;
        #pragma unroll
        for (int c = 0; c < Cc; c += 4)
            *reinterpret_cast<float4*>(rp1 + c) =
                make_float4(v[c], v[c + 1], v[c + 2], v[c + 3]);
    }
    __syncthreads();
    // Stage 2: warps 0..7 fold their own accumulators into red[wid].
    if (wid < RSETS) {
        float v[Cc];
        #pragma unroll
        for (int p = 0; p < 8; p++) unpack2(a0[p], v[2 * p], v[2 * p + 1]);
        float* rp0 = red + ((size_t)wid * MTILE + lane) * Cc;
        #pragma unroll
        for (int c = 0; c < Cc; c += 4) {
            float4 old = *reinterpret_cast<const float4*>(rp0 + c);
            *reinterpret_cast<float4*>(rp0 + c) =
                make_float4(old.x + v[c], old.y + v[c + 1],
                            old.z + v[c + 2], old.w + v[c + 3]);
        }
        #pragma unroll
        for (int p = 0; p < 8; p++) unpack2(a1[p], v[2 * p], v[2 * p + 1]);
        float* rp1 = red + ((size_t)wid * MTILE + lane + 32) * Cc;
        #pragma unroll
        for (int c = 0; c < Cc; c += 4) {
            float4 old = *reinterpret_cast<const float4*>(rp1 + c);
            *reinterpret_cast<float4*>(rp1 + c) =
                make_float4(old.x + v[c], old.y + v[c + 1],
                            old.z + v[c + 2], old.w + v[c + 3]);
        }
    }
    __syncthreads();

    // Stage 3: tree-reduce 8 sets into red[0..MTILE*Cc).
    {
        float4* rv = reinterpret_cast<float4*>(red);
        const int NV = MTILE * Cc / 4;   // 256 slots
        if (t < NV) {
            float4 s = rv[t];
            #pragma unroll
            for (int w = 1; w < RSETS; w++) {
                float4 p = rv[w * NV + t];
                s.x += p.x; s.y += p.y; s.z += p.z; s.w += p.w;
            }
            rv[t] = s;
        }
    }
    __syncthreads();

    // linear C -> OUT_C: thread t -> (ml = t>>3, 4 outputs at og=(t&7)*4)
    {
        const int ml = t >> 3;            // 0..63
        const int og = (t & 7) * 4;       // 0..28
        const float* z = red + ml * Cc;
        float4 o4;
        o4.x = __ldg(lb + og + 0); o4.y = __ldg(lb + og + 1);
        o4.z = __ldg(lb + og + 2); o4.w = __ldg(lb + og + 3);
        #pragma unroll
        for (int c = 0; c < Cc; c++) {
            float zc = z[c];
            o4.x += zc * shlw[(og + 0) * Cc + c];
            o4.y += zc * shlw[(og + 1) * Cc + c];
            o4.z += zc * shlw[(og + 2) * Cc + c];
            o4.w += zc * shlw[(og + 3) * Cc + c];
        }
        *reinterpret_cast<float4*>(
            out + (((size_t)b * NOUT) + mt * MTILE + ml) * OUTC + og) = o4;
    }
}

// ---------------------------------------------------------------------------
// Launch. Inputs (metadata order):
// 0 r (8,16,512) | 1 x_context (8,512,1) | 2 y_context (unused) |
// 3 x_target (8,1024,1) | 4 conv_w (16,16,5) | 5 conv_b (16) |
// 6 sigma (16) | 7 lin_w (32,16) | 8 lin_b (32)  -> out (8,1024,32) f32
// ---------------------------------------------------------------------------
extern "C" void kernel_launch(void* const* d_in, const int* in_sizes, int n_in,
                              void* d_out, int out_size) {
    const float* r      = (const float*)d_in[0];
    const float* xc     = (const float*)d_in[1];
    const float* xt     = (const float*)d_in[3];
    const float* conv_w = (const float*)d_in[4];
    const float* conv_b = (const float*)d_in[5];
    const float* sigma  = (const float*)d_in[6];
    const float* lin_w  = (const float*)d_in[7];
    const float* lin_b  = (const float*)d_in[8];
    float* out = (float*)d_out;

    conv_kernel<<<dim3(NIN / CNTILE, Bq), CTHREADS>>>(r, conv_w, conv_b);
    gauss_lin_kernel<<<dim3(MT, Bq), GTHREADS>>>(xc, xt, sigma, lin_w, lin_b, out);
}

// round 5
// speedup vs baseline: 1.0332x; 1.0332x over previous
#include <cuda_runtime.h>
#include <cstdint>

// Problem constants
#define Bq     8
#define NIN    512
#define NOUT   1024
#define Cc     16
#define OUTC   32
#define KW     5

// Conv tiling
#define CNTILE 32
#define CTHREADS 128

// Fused gauss+linear tiling
#define MTILE  64                 // m targets per block (2 per thread)
#define MT     (NOUT / MTILE)     // 16
#define GWARPS 16
#define NPW    (NIN / GWARPS)     // 32
#define GTHREADS (GWARPS * 32)    // 512
#define RSETS  8                  // partial sets in smem (staged reduce)
#define CHUNK  8                  // software-pipeline chunk (n per phase)

#define LOG2E 1.4426950408889634f

__device__ float g_rt[Bq * NIN * Cc];   // conv output [b][n][c]

__device__ __forceinline__ void ffma2(uint64_t& d, uint64_t a, uint64_t b) {
    asm("fma.rn.f32x2 %0, %1, %2, %0;" : "+l"(d) : "l"(a), "l"(b));
}
__device__ __forceinline__ uint64_t pack2(float lo, float hi) {
    uint64_t r; asm("mov.b64 %0, {%1, %2};" : "=l"(r) : "f"(lo), "f"(hi)); return r;
}
__device__ __forceinline__ void unpack2(uint64_t v, float& lo, float& hi) {
    asm("mov.b64 {%0, %1}, %2;" : "=f"(lo), "=f"(hi) : "l"(v));
}
__device__ __forceinline__ float ex2a(float x) {
    float r; asm("ex2.approx.f32 %0, %1;" : "=f"(r) : "f"(x)); return r;
}

// ---------------------------------------------------------------------------
// Kernel 1: Conv1d (NCH, OIH, SAME pad=2) + bias -> g_rt[b][n][c]
// grid (NIN/CNTILE, B) = (16, 8) = 128 blocks, block 128.
// thread: nl = t & 31, cg = t >> 5 (4 out-channels each)
// ---------------------------------------------------------------------------
__global__ void conv_kernel(const float* __restrict__ r,
                            const float* __restrict__ w,
                            const float* __restrict__ bias) {
    __shared__ float sr[Cc][CNTILE + 4];
    __shared__ float sws[Cc * KW * Cc];   // [ci][k][c_out]
    __shared__ float sb[Cc];

    const int b  = blockIdx.y;
    const int n0 = blockIdx.x * CNTILE;
    const int t  = threadIdx.x;

    for (int i = t; i < Cc * (CNTILE + 4); i += CTHREADS) {
        int ci = i / (CNTILE + 4);
        int j  = i % (CNTILE + 4);
        int n  = n0 + j - 2;
        sr[ci][j] = (n >= 0 && n < NIN) ? r[((size_t)b * Cc + ci) * NIN + n] : 0.0f;
    }
    for (int i = t; i < Cc * Cc * KW; i += CTHREADS) {
        int c  = i / (Cc * KW);
        int rm = i % (Cc * KW);
        int ci = rm / KW;
        int k  = rm % KW;
        sws[(ci * KW + k) * Cc + c] = w[i];
    }
    if (t < Cc) sb[t] = bias[t];
    __syncthreads();

    const int nl = t & (CNTILE - 1);
    const int cg = t >> 5;            // 0..3

    float4 a;
    a.x = sb[cg * 4 + 0]; a.y = sb[cg * 4 + 1];
    a.z = sb[cg * 4 + 2]; a.w = sb[cg * 4 + 3];

    #pragma unroll
    for (int k = 0; k < KW; k++) {
        #pragma unroll
        for (int ci = 0; ci < Cc; ci++) {
            float v = sr[ci][nl + k];
            float4 wv = *reinterpret_cast<const float4*>(&sws[(ci * KW + k) * Cc + cg * 4]);
            a.x += v * wv.x; a.y += v * wv.y; a.z += v * wv.z; a.w += v * wv.w;
        }
    }

    *reinterpret_cast<float4*>(g_rt + ((size_t)b * NIN + n0 + nl) * Cc + cg * 4) = a;
}

// ---------------------------------------------------------------------------
// Kernel 2: fused Gaussian transform + staged reduce + pointwise linear.
// grid (MT, B) = (16, 8) = 128 blocks, block 512 (16 warps).
// Warp = n-chunk of 32, lane = m-pair {m0, m1 = m0+32}.
// Hot loop is software-pipelined in chunks of 8 n: phase A computes 16
// independent exps; phase B is a pure LDS.128 + FFMA2 stream.
// ---------------------------------------------------------------------------
__global__ void __launch_bounds__(GTHREADS, 1)
gauss_lin_kernel(const float* __restrict__ xc,
                 const float* __restrict__ xt,
                 const float* __restrict__ sigma,
                 const float* __restrict__ lw,
                 const float* __restrict__ lb,
                 float* __restrict__ out) {
    __shared__ float shx[NIN];                                 // 2 KB
    __shared__ __align__(16) float shrt[NIN][Cc];              // 32 KB
    __shared__ __align__(16) float red[RSETS * MTILE * Cc];    // 32 KB
    __shared__ float shlw[OUTC * Cc];                          // 2 KB
    __shared__ float sh_nh[Cc];
    __shared__ int   sh_alleq;

    const int b  = blockIdx.y;
    const int mt = blockIdx.x;
    const int t  = threadIdx.x;
    const int lane = t & 31;
    const int wid  = t >> 5;

    if (t < Cc) {
        float sg = sigma[t];
        sh_nh[t] = -0.5f * expf(-2.0f * sg) * LOG2E;  // fold log2e for ex2
    }
    if (t == 0) {
        float s0 = sigma[0];
        int eq = 1;
        #pragma unroll
        for (int c = 1; c < Cc; c++) eq &= (sigma[c] == s0);
        sh_alleq = eq;
    }
    for (int i = t; i < NIN; i += GTHREADS) shx[i] = xc[(size_t)b * NIN + i];
    {
        const float4* src = reinterpret_cast<const float4*>(g_rt + (size_t)b * NIN * Cc);
        float4* dst = reinterpret_cast<float4*>(&shrt[0][0]);
        #pragma unroll
        for (int i = t; i < NIN * Cc / 4; i += GTHREADS) dst[i] = src[i];
    }
    for (int i = t; i < OUTC * Cc; i += GTHREADS) shlw[i] = lw[i];
    __syncthreads();

    const int m0 = mt * MTILE + lane;
    const int m1 = m0 + 32;
    const float xm0 = xt[(size_t)b * NOUT + m0];
    const float xm1 = xt[(size_t)b * NOUT + m1];

    uint64_t a0[8], a1[8];
    #pragma unroll
    for (int p = 0; p < 8; p++) { a0[p] = 0ull; a1[p] = 0ull; }

    const int n0 = wid * NPW;

    if (sh_alleq) {
        const float nh = sh_nh[0];
        #pragma unroll
        for (int ch = 0; ch < NPW; ch += CHUNK) {
            // Phase A: 16 independent exps (8 n x 2 m) — pipelined LDS+MUFU
            uint64_t e0p[CHUNK], e1p[CHUNK];
            #pragma unroll
            for (int j = 0; j < CHUNK; j++) {
                const float xn = shx[n0 + ch + j];
                float d0 = xm0 - xn, d1 = xm1 - xn;
                float e0 = ex2a(d0 * d0 * nh);
                float e1 = ex2a(d1 * d1 * nh);
                e0p[j] = pack2(e0, e0);
                e1p[j] = pack2(e1, e1);
            }
            // Phase B: pure LDS.128 + FFMA2 stream
            #pragma unroll
            for (int j = 0; j < CHUNK; j++) {
                const ulonglong2* rp =
                    reinterpret_cast<const ulonglong2*>(shrt[n0 + ch + j]);
                ulonglong2 q0 = rp[0], q1 = rp[1], q2 = rp[2], q3 = rp[3];
                ffma2(a0[0], e0p[j], q0.x); ffma2(a0[1], e0p[j], q0.y);
                ffma2(a0[2], e0p[j], q1.x); ffma2(a0[3], e0p[j], q1.y);
                ffma2(a0[4], e0p[j], q2.x); ffma2(a0[5], e0p[j], q2.y);
                ffma2(a0[6], e0p[j], q3.x); ffma2(a0[7], e0p[j], q3.y);
                ffma2(a1[0], e1p[j], q0.x); ffma2(a1[1], e1p[j], q0.y);
                ffma2(a1[2], e1p[j], q1.x); ffma2(a1[3], e1p[j], q1.y);
                ffma2(a1[4], e1p[j], q2.x); ffma2(a1[5], e1p[j], q2.y);
                ffma2(a1[6], e1p[j], q3.x); ffma2(a1[7], e1p[j], q3.y);
            }
        }
    } else {
        float nh[Cc];
        #pragma unroll
        for (int c = 0; c < Cc; c++) nh[c] = sh_nh[c];
        for (int i = 0; i < NPW; i++) {
            const int n = n0 + i;
            const float xn = shx[n];
            float d0 = (xm0 - xn) * (xm0 - xn);
            float d1 = (xm1 - xn) * (xm1 - xn);
            const ulonglong2* rp = reinterpret_cast<const ulonglong2*>(shrt[n]);
            ulonglong2 q[4] = {rp[0], rp[1], rp[2], rp[3]};
            #pragma unroll
            for (int p = 0; p < 8; p++) {
                uint64_t qv = (p & 1) ? ((const ulonglong2*)q)[p >> 1].y
                                      : ((const ulonglong2*)q)[p >> 1].x;
                uint64_t e0p = pack2(ex2a(d0 * nh[2 * p]), ex2a(d0 * nh[2 * p + 1]));
                uint64_t e1p = pack2(ex2a(d1 * nh[2 * p]), ex2a(d1 * nh[2 * p + 1]));
                ffma2(a0[p], e0p, qv);
                ffma2(a1[p], e1p, qv);
            }
        }
    }

    // --- staged reduction into RSETS=8 partial sets -------------------------
    if (wid >= RSETS) {
        float v[Cc];
        #pragma unroll
        for (int p = 0; p < 8; p++) unpack2(a0[p], v[2 * p], v[2 * p + 1]);
        float* rp0 = red + ((size_t)(wid - RSETS) * MTILE + lane) * Cc;
        #pragma unroll
        for (int c = 0; c < Cc; c += 4)
            *reinterpret_cast<float4*>(rp0 + c) =
                make_float4(v[c], v[c + 1], v[c + 2], v[c + 3]);
        #pragma unroll
        for (int p = 0; p < 8; p++) unpack2(a1[p], v[2 * p], v[2 * p + 1]);
        float* rp1 = red + ((size_t)(wid - RSETS) * MTILE + lane + 32) * Cc;
        #pragma unroll
        for (int c = 0; c < Cc; c += 4)
            *reinterpret_cast<float4*>(rp1 + c) =
                make_float4(v[c], v[c + 1], v[c + 2], v[c + 3]);
    }
    __syncthreads();
    if (wid < RSETS) {
        float v[Cc];
        #pragma unroll
        for (int p = 0; p < 8; p++) unpack2(a0[p], v[2 * p], v[2 * p + 1]);
        float* rp0 = red + ((size_t)wid * MTILE + lane) * Cc;
        #pragma unroll
        for (int c = 0; c < Cc; c += 4) {
            float4 old = *reinterpret_cast<const float4*>(rp0 + c);
            *reinterpret_cast<float4*>(rp0 + c) =
                make_float4(old.x + v[c], old.y + v[c + 1],
                            old.z + v[c + 2], old.w + v[c + 3]);
        }
        #pragma unroll
        for (int p = 0; p < 8; p++) unpack2(a1[p], v[2 * p], v[2 * p + 1]);
        float* rp1 = red + ((size_t)wid * MTILE + lane + 32) * Cc;
        #pragma unroll
        for (int c = 0; c < Cc; c += 4) {
            float4 old = *reinterpret_cast<const float4*>(rp1 + c);
            *reinterpret_cast<float4*>(rp1 + c) =
                make_float4(old.x + v[c], old.y + v[c + 1],
                            old.z + v[c + 2], old.w + v[c + 3]);
        }
    }
    __syncthreads();

    // tree-reduce 8 sets into red[0..MTILE*Cc)
    {
        float4* rv = reinterpret_cast<float4*>(red);
        const int NV = MTILE * Cc / 4;   // 256 slots
        if (t < NV) {
            float4 s = rv[t];
            #pragma unroll
            for (int w = 1; w < RSETS; w++) {
                float4 p = rv[w * NV + t];
                s.x += p.x; s.y += p.y; s.z += p.z; s.w += p.w;
            }
            rv[t] = s;
        }
    }
    __syncthreads();

    // linear C -> OUT_C: thread t -> (ml = t>>3, 4 outputs at og=(t&7)*4)
    {
        const int ml = t >> 3;            // 0..63
        const int og = (t & 7) * 4;       // 0..28
        const float* z = red + ml * Cc;
        float4 o4;
        o4.x = __ldg(lb + og + 0); o4.y = __ldg(lb + og + 1);
        o4.z = __ldg(lb + og + 2); o4.w = __ldg(lb + og + 3);
        #pragma unroll
        for (int c = 0; c < Cc; c++) {
            float zc = z[c];
            o4.x += zc * shlw[(og + 0) * Cc + c];
            o4.y += zc * shlw[(og + 1) * Cc + c];
            o4.z += zc * shlw[(og + 2) * Cc + c];
            o4.w += zc * shlw[(og + 3) * Cc + c];
        }
        *reinterpret_cast<float4*>(
            out + (((size_t)b * NOUT) + mt * MTILE + ml) * OUTC + og) = o4;
    }
}

// ---------------------------------------------------------------------------
// Launch. Inputs (metadata order):
// 0 r (8,16,512) | 1 x_context (8,512,1) | 2 y_context (unused) |
// 3 x_target (8,1024,1) | 4 conv_w (16,16,5) | 5 conv_b (16) |
// 6 sigma (16) | 7 lin_w (32,16) | 8 lin_b (32)  -> out (8,1024,32) f32
// ---------------------------------------------------------------------------
extern "C" void kernel_launch(void* const* d_in, const int* in_sizes, int n_in,
                              void* d_out, int out_size) {
    const float* r      = (const float*)d_in[0];
    const float* xc     = (const float*)d_in[1];
    const float* xt     = (const float*)d_in[3];
    const float* conv_w = (const float*)d_in[4];
    const float* conv_b = (const float*)d_in[5];
    const float* sigma  = (const float*)d_in[6];
    const float* lin_w  = (const float*)d_in[7];
    const float* lin_b  = (const float*)d_in[8];
    float* out = (float*)d_out;

    conv_kernel<<<dim3(NIN / CNTILE, Bq), CTHREADS>>>(r, conv_w, conv_b);
    gauss_lin_kernel<<<dim3(MT, Bq), GTHREADS>>>(xc, xt, sigma, lin_w, lin_b, out);
}